// round 1
// baseline (speedup 1.0000x reference)
#include <cuda_runtime.h>
#include <cuda_bf16.h>
#include <cstdint>

// ----------------------------------------------------------------------------
// SnakeHead: bilinear sample -> 6x dilated Conv1D (K=3, bias+ReLU) -> 1x1 head
// Round 1: fp32 SIMT baseline. Conv as register-tiled GEMM (BM=BN=128, BK=16,
// 8x8 micro-tile per thread, packed fma.rn.f32x2 accumulation, double-buffered
// SMEM with register-staged global prefetch).
// ----------------------------------------------------------------------------

#define BDIM   8
#define NDIM   1024
#define HDIM   256
#define WDIM   256
#define CDIM   256
#define HID    512

// Ping-pong activation scratch: [8, 1024, 512] fp32 each (16 MB each).
__device__ float g_buf0[BDIM * NDIM * HID];
__device__ float g_buf1[BDIM * NDIM * HID];

// ---------------- packed f32x2 helpers ----------------
__device__ __forceinline__ unsigned long long pk2(float v) {
    unsigned long long r;
    asm("mov.b64 %0, {%1, %2};" : "=l"(r) : "f"(v), "f"(v));
    return r;
}
__device__ __forceinline__ void fma2(unsigned long long& d,
                                     unsigned long long a,
                                     unsigned long long b) {
    asm("fma.rn.f32x2 %0, %1, %2, %0;" : "+l"(d) : "l"(a), "l"(b));
}
__device__ __forceinline__ float2 upk(unsigned long long v) {
    float2 f;
    asm("mov.b64 {%0, %1}, %2;" : "=f"(f.x), "=f"(f.y) : "l"(v));
    return f;
}

// ---------------- bilinear sampling ----------------
// grid: (B*N) blocks, 256 threads (one per channel). out: [B, N, 256]
__global__ void sample_kernel(const float* __restrict__ vtx,
                              const float* __restrict__ feat,
                              float* __restrict__ out) {
    int p = blockIdx.x;                 // 0 .. B*N-1
    int b = p >> 10;
    float y = vtx[2 * p + 0];
    float x = vtx[2 * p + 1];
    float y0f = floorf(y), x0f = floorf(x);
    int y0 = (int)y0f, x0 = (int)x0f;
    float wy1 = y - y0f, wx1 = x - x0f;
    float wy0 = 1.0f - wy1, wx0 = 1.0f - wx1;

    int c = threadIdx.x;
    const float* fb = feat + (size_t)b * HDIM * WDIM * CDIM;
    float acc = 0.0f;

    int ys[2] = {y0, y0 + 1};
    int xs[2] = {x0, x0 + 1};
    float wy[2] = {wy0, wy1};
    float wx[2] = {wx0, wx1};
#pragma unroll
    for (int iy = 0; iy < 2; ++iy) {
#pragma unroll
        for (int ix = 0; ix < 2; ++ix) {
            int yi = ys[iy], xi = xs[ix];
            float w = wy[iy] * wx[ix];
            if (yi >= 0 && yi < HDIM && xi >= 0 && xi < WDIM) {
                acc += w * fb[((size_t)yi * WDIM + xi) * CDIM + c];
            }
        }
    }
    out[(size_t)p * CDIM + c] = acc;
}

// ---------------- dilated conv1d as GEMM ----------------
// in : [B, N, CIN]   w : [3, CIN, HID]   bias : [HID]   out : [B, N, HID]
// y[b,n,co] = relu( bias[co] + sum_{k,ci} in[b, n+(k-1)*rate, ci] * w[k,ci,co] )
template <int CIN>
__global__ __launch_bounds__(256) void conv_kernel(
    const float* __restrict__ in, const float* __restrict__ wgt,
    const float* __restrict__ bias, float* __restrict__ out, int rate) {
    constexpr int BM = 128, BN = 128, BK = 16;
    constexpr int KTOT = 3 * CIN;
    constexpr int NCHUNK = KTOT / BK;

    __shared__ float As[2][BK][BM + 4];   // [ci][row], padded
    __shared__ float Bs[2][BK][BN];       // [ci][col]

    const int b   = blockIdx.z;
    const int n0  = blockIdx.y * BM;
    const int co0 = blockIdx.x * BN;
    const int tid = threadIdx.x;

    // loader mapping
    const int arow = tid >> 1;            // 0..127
    const int aci  = (tid & 1) * 8;       // 0 or 8
    const int bci  = tid >> 4;            // 0..15
    const int bcol = (tid & 15) * 8;      // 0,8,...,120
    // compute mapping: 16x16 grid of threads, 8x8 outputs each
    const int tr = tid >> 4;              // row group
    const int tc = tid & 15;              // col group

    unsigned long long acc[8][4];
#pragma unroll
    for (int i = 0; i < 8; ++i)
#pragma unroll
        for (int j = 0; j < 4; ++j) acc[i][j] = 0ULL;

    float4 ra0, ra1, rb0, rb1;

    auto loadChunk = [&](int cn) {
        const int tap = (cn * BK) / CIN;
        const int ci0 = cn * BK - tap * CIN;
        const int n = n0 + arow + (tap - 1) * rate;
        if ((unsigned)n < (unsigned)NDIM) {
            const float* p =
                in + ((size_t)b * NDIM + n) * CIN + (ci0 + aci);
            ra0 = *(const float4*)p;
            ra1 = *(const float4*)(p + 4);
        } else {
            ra0 = make_float4(0.f, 0.f, 0.f, 0.f);
            ra1 = make_float4(0.f, 0.f, 0.f, 0.f);
        }
        const float* q =
            wgt + ((size_t)(tap * CIN + ci0 + bci)) * HID + (co0 + bcol);
        rb0 = *(const float4*)q;
        rb1 = *(const float4*)(q + 4);
    };

    auto storeChunk = [&](int nb) {
        As[nb][aci + 0][arow] = ra0.x;
        As[nb][aci + 1][arow] = ra0.y;
        As[nb][aci + 2][arow] = ra0.z;
        As[nb][aci + 3][arow] = ra0.w;
        As[nb][aci + 4][arow] = ra1.x;
        As[nb][aci + 5][arow] = ra1.y;
        As[nb][aci + 6][arow] = ra1.z;
        As[nb][aci + 7][arow] = ra1.w;
        *(float4*)&Bs[nb][bci][bcol]     = rb0;
        *(float4*)&Bs[nb][bci][bcol + 4] = rb1;
    };

    // prologue
    loadChunk(0);
    storeChunk(0);
    __syncthreads();

    int buf = 0;
    for (int c = 0; c < NCHUNK; ++c) {
        const bool more = (c + 1 < NCHUNK);
        if (more) loadChunk(c + 1);

#pragma unroll
        for (int ci = 0; ci < BK; ++ci) {
            float4 av0 = *(const float4*)&As[buf][ci][tr * 8];
            float4 av1 = *(const float4*)&As[buf][ci][tr * 8 + 4];
            ulonglong2 bq0 = *(const ulonglong2*)&Bs[buf][ci][tc * 8];
            ulonglong2 bq1 = *(const ulonglong2*)&Bs[buf][ci][tc * 8 + 4];
            unsigned long long bb[4] = {bq0.x, bq0.y, bq1.x, bq1.y};
            float aa[8] = {av0.x, av0.y, av0.z, av0.w,
                           av1.x, av1.y, av1.z, av1.w};
#pragma unroll
            for (int i = 0; i < 8; ++i) {
                unsigned long long a2 = pk2(aa[i]);
                fma2(acc[i][0], a2, bb[0]);
                fma2(acc[i][1], a2, bb[1]);
                fma2(acc[i][2], a2, bb[2]);
                fma2(acc[i][3], a2, bb[3]);
            }
        }

        if (more) {
            storeChunk(buf ^ 1);
            __syncthreads();
            buf ^= 1;
        }
    }

    // epilogue: bias + relu + store
    float4 bv0 = *(const float4*)&bias[co0 + tc * 8];
    float4 bv1 = *(const float4*)&bias[co0 + tc * 8 + 4];
    float bv[8] = {bv0.x, bv0.y, bv0.z, bv0.w, bv1.x, bv1.y, bv1.z, bv1.w};

#pragma unroll
    for (int i = 0; i < 8; ++i) {
        const int r = n0 + tr * 8 + i;
        float* op = out + ((size_t)b * NDIM + r) * HID + co0 + tc * 8;
        float2 p0 = upk(acc[i][0]);
        float2 p1 = upk(acc[i][1]);
        float2 p2 = upk(acc[i][2]);
        float2 p3 = upk(acc[i][3]);
        float4 o0 = make_float4(fmaxf(p0.x + bv[0], 0.f),
                                fmaxf(p0.y + bv[1], 0.f),
                                fmaxf(p1.x + bv[2], 0.f),
                                fmaxf(p1.y + bv[3], 0.f));
        float4 o1 = make_float4(fmaxf(p2.x + bv[4], 0.f),
                                fmaxf(p2.y + bv[5], 0.f),
                                fmaxf(p3.x + bv[6], 0.f),
                                fmaxf(p3.y + bv[7], 0.f));
        *(float4*)op       = o0;
        *(float4*)(op + 4) = o1;
    }
}

// ---------------- offset head: 1x1 conv (512 -> 2) + vertex add ----------------
// grid: B*N/8 blocks of 256 threads; one warp per vertex.
__global__ void head_kernel(const float* __restrict__ h,
                            const float* __restrict__ w_off,
                            const float* __restrict__ vtx,
                            float* __restrict__ out) {
    __shared__ float wsh[HID * 2];
    const int tid = threadIdx.x;
    for (int i = tid; i < HID * 2; i += 256) wsh[i] = w_off[i];
    __syncthreads();

    const int warp = tid >> 5, lane = tid & 31;
    const int p = blockIdx.x * 8 + warp;
    const float* hp = h + (size_t)p * HID;

    float s0 = 0.f, s1 = 0.f;
#pragma unroll
    for (int i = lane; i < HID; i += 32) {
        float v = hp[i];
        s0 += v * wsh[2 * i + 0];
        s1 += v * wsh[2 * i + 1];
    }
#pragma unroll
    for (int o = 16; o > 0; o >>= 1) {
        s0 += __shfl_down_sync(0xFFFFFFFFu, s0, o);
        s1 += __shfl_down_sync(0xFFFFFFFFu, s1, o);
    }
    if (lane == 0) {
        out[2 * p + 0] = vtx[2 * p + 0] + s0;
        out[2 * p + 1] = vtx[2 * p + 1] + s1;
    }
}

// ---------------- launch ----------------
extern "C" void kernel_launch(void* const* d_in, const int* in_sizes, int n_in,
                              void* d_out, int out_size) {
    (void)in_sizes; (void)n_in; (void)out_size;
    const float* vertices = (const float*)d_in[0];
    const float* features = (const float*)d_in[1];
    const float* w[6];
    const float* bb[6];
    for (int i = 0; i < 6; ++i) {
        w[i]  = (const float*)d_in[2 + 2 * i];
        bb[i] = (const float*)d_in[3 + 2 * i];
    }
    const float* w_off = (const float*)d_in[14];

    float *buf0 = nullptr, *buf1 = nullptr;
    cudaGetSymbolAddress((void**)&buf0, g_buf0);
    cudaGetSymbolAddress((void**)&buf1, g_buf1);

    // 1) bilinear sampling -> buf0 [8,1024,256]
    sample_kernel<<<BDIM * NDIM, 256>>>(vertices, features, buf0);

    // 2) conv stack (rates 1,3,9,9,3,1), ping-pong buffers
    dim3 grid(HID / 128, NDIM / 128, BDIM);
    conv_kernel<CDIM><<<grid, 256>>>(buf0, w[0], bb[0], buf1, 1);
    conv_kernel<HID ><<<grid, 256>>>(buf1, w[1], bb[1], buf0, 3);
    conv_kernel<HID ><<<grid, 256>>>(buf0, w[2], bb[2], buf1, 9);
    conv_kernel<HID ><<<grid, 256>>>(buf1, w[3], bb[3], buf0, 9);
    conv_kernel<HID ><<<grid, 256>>>(buf0, w[4], bb[4], buf1, 3);
    conv_kernel<HID ><<<grid, 256>>>(buf1, w[5], bb[5], buf0, 1);

    // 3) offset head + vertex add -> d_out [8,1024,2]
    head_kernel<<<BDIM * NDIM / 8, 256>>>(buf0, w_off, vertices,
                                          (float*)d_out);
}

// round 3
// speedup vs baseline: 5.0415x; 5.0415x over previous
#include <cuda_runtime.h>
#include <cuda_bf16.h>
#include <cstdint>

// ----------------------------------------------------------------------------
// SnakeHead round 3: bf16 mma.sync (HMMA) conv stack.
// NOTE: harness compiles for base sm_100 (NOT sm_100a) -> no tcgen05/TMEM.
// Fallback: Ampere-style pipeline: cp.async (3-buffer) + ldmatrix + 
// mma.sync.m16n8k16.bf16, fp32 accum, fused bias+ReLU, bf16 activations.
// CTA tile 128x128, BK=32, 8 warps (warp tile 32x64).
// ----------------------------------------------------------------------------

#define BDIM 8
#define NDIM 1024
#define HDIM 256
#define WDIM 256
#define CDIM 256
#define HID  512
#define MTOT (BDIM * NDIM)

// activations (bf16 stored as ushort): ping-pong
__device__ unsigned short g_act0[MTOT * HID];
__device__ unsigned short g_act1[MTOT * HID];
// transposed bf16 weights: [layer][cout=512][ktot<=1536]
__device__ unsigned short g_wt[6][HID * 3 * HID];

// ---------------- PTX helpers ----------------
__device__ __forceinline__ uint32_t smem_u32(const void* p) {
    uint32_t a;
    asm("{ .reg .u64 t; cvta.to.shared.u64 t, %1; cvt.u32.u64 %0, t; }"
        : "=r"(a) : "l"(p));
    return a;
}
__device__ __forceinline__ void cp16(uint32_t dst, const void* src, int sz) {
    asm volatile("cp.async.cg.shared.global [%0], [%1], 16, %2;"
                 :: "r"(dst), "l"(src), "r"(sz));
}
#define CP_COMMIT() asm volatile("cp.async.commit_group;" ::: "memory")
#define CP_WAIT1()  asm volatile("cp.async.wait_group 1;" ::: "memory")
#define CP_WAIT0()  asm volatile("cp.async.wait_group 0;" ::: "memory")

__device__ __forceinline__ void ldsm4(uint32_t* r, uint32_t addr) {
    asm volatile("ldmatrix.sync.aligned.m8n8.x4.shared.b16 {%0,%1,%2,%3}, [%4];"
                 : "=r"(r[0]), "=r"(r[1]), "=r"(r[2]), "=r"(r[3]) : "r"(addr));
}
__device__ __forceinline__ void mma16816(float* c, const uint32_t* a,
                                         const uint32_t* b) {
    asm volatile(
        "mma.sync.aligned.m16n8k16.row.col.f32.bf16.bf16.f32 "
        "{%0,%1,%2,%3}, {%4,%5,%6,%7}, {%8,%9}, {%0,%1,%2,%3};"
        : "+f"(c[0]), "+f"(c[1]), "+f"(c[2]), "+f"(c[3])
        : "r"(a[0]), "r"(a[1]), "r"(a[2]), "r"(a[3]), "r"(b[0]), "r"(b[1]));
}

// ---------------- weight transpose+convert: [KTOT,512] f32 -> [512,KTOT] bf16
__global__ void wconv_kernel(const float* __restrict__ w,
                             unsigned short* __restrict__ wt, int ktot) {
    __shared__ float t[32][33];
    const int k0 = blockIdx.x * 32, c0 = blockIdx.y * 32;
    const int tx = threadIdx.x, ty = threadIdx.y;
#pragma unroll
    for (int i = ty; i < 32; i += 8)
        t[i][tx] = w[(size_t)(k0 + i) * HID + c0 + tx];
    __syncthreads();
#pragma unroll
    for (int i = ty; i < 32; i += 8) {
        __nv_bfloat16 v = __float2bfloat16(t[tx][i]);
        wt[(size_t)(c0 + i) * ktot + k0 + tx] = *(unsigned short*)&v;
    }
}

// ---------------- bilinear sampling (fp32 gather -> bf16) ----------------
__global__ void sample_kernel(const float* __restrict__ vtx,
                              const float* __restrict__ feat,
                              unsigned short* __restrict__ out) {
    const int p = blockIdx.x * 4 + (threadIdx.x >> 6);
    const int l = threadIdx.x & 63;
    const int b = p >> 10;
    const float y = vtx[2 * p + 0];
    const float x = vtx[2 * p + 1];
    const float y0f = floorf(y), x0f = floorf(x);
    const int y0 = (int)y0f, x0 = (int)x0f;
    const float wy1 = y - y0f, wx1 = x - x0f;
    const float wy0 = 1.0f - wy1, wx0 = 1.0f - wx1;

    const float* fb = feat + (size_t)b * HDIM * WDIM * CDIM + l * 4;
    float4 acc = make_float4(0.f, 0.f, 0.f, 0.f);
    const int ys[2] = {y0, y0 + 1};
    const int xs[2] = {x0, x0 + 1};
    const float wy[2] = {wy0, wy1};
    const float wx[2] = {wx0, wx1};
#pragma unroll
    for (int iy = 0; iy < 2; ++iy)
#pragma unroll
        for (int ix = 0; ix < 2; ++ix) {
            const int yi = ys[iy], xi = xs[ix];
            const float w = wy[iy] * wx[ix];
            if (yi >= 0 && yi < HDIM && xi >= 0 && xi < WDIM) {
                const float4 v = *(const float4*)(fb + ((size_t)yi * WDIM + xi) * CDIM);
                acc.x += w * v.x; acc.y += w * v.y;
                acc.z += w * v.z; acc.w += w * v.w;
            }
        }
    __nv_bfloat162 h0 = __floats2bfloat162_rn(acc.x, acc.y);
    __nv_bfloat162 h1 = __floats2bfloat162_rn(acc.z, acc.w);
    uint2 st = make_uint2(*(uint32_t*)&h0, *(uint32_t*)&h1);
    *(uint2*)(out + (size_t)p * CDIM + l * 4) = st;
}

// ---------------- dilated conv1d as HMMA GEMM ----------------
// in: bf16 [MTOT, CIN], wt: bf16 [512, 3*CIN] (k-contiguous rows),
// bias fp32[512], out: bf16 [MTOT, 512].
// CTA tile M=128 N=128, BK=32 bf16. smem rows padded to 80B (conflict-free
// ldmatrix). 3 stages x (A 10KB + B 10KB) = 60KB dynamic smem.
template <int CIN>
__global__ __launch_bounds__(256, 2) void conv_mma(
    const unsigned short* __restrict__ in, const unsigned short* __restrict__ wt,
    const float* __restrict__ bias, unsigned short* __restrict__ outp, int rate) {
    constexpr int KTOT = 3 * CIN;
    constexpr int NC = KTOT / 32;
    constexpr int STG = 20480;      // bytes per stage (A 10240 + B 10240)

    extern __shared__ __align__(128) char smem[];
    const uint32_t sb = smem_u32(smem);
    const int tid = threadIdx.x;
    const int wid = tid >> 5;
    const int lane = tid & 31;
    const int m0 = blockIdx.x * 128;
    const int b = m0 >> 10;
    const int nloc0 = m0 & (NDIM - 1);
    const int n0 = blockIdx.y * 128;
    const int warp_m = wid & 3;     // 4 x 32 rows
    const int warp_n = wid >> 2;    // 2 x 64 cols

    float acc[2][8][4];
#pragma unroll
    for (int i = 0; i < 2; ++i)
#pragma unroll
        for (int j = 0; j < 8; ++j)
#pragma unroll
            for (int q = 0; q < 4; ++q) acc[i][j][q] = 0.f;

    const int lrow = tid >> 1;            // 0..127
    const int loff = (tid & 1) * 32;      // 0 or 32 bytes

    auto loadChunk = [&](int c) {
        const int tap = (c * 32) / CIN;
        const int ci0 = c * 32 - tap * CIN;
        const uint32_t stA = sb + (c % 3) * STG;
        const uint32_t stB = stA + 10240;
        // A: 128 rows x 64B (padded to 80B)
        const int n = nloc0 + lrow + (tap - 1) * rate;
        const char* srcA =
            (const char*)(in + ((size_t)(b * NDIM) + n) * CIN + ci0) + loff;
        const int ok = ((unsigned)n < (unsigned)NDIM) ? 16 : 0;
        cp16(stA + lrow * 80 + loff, srcA, ok);
        cp16(stA + lrow * 80 + loff + 16, srcA + 16, ok);
        // B: 128 rows x 64B
        const char* srcB =
            (const char*)(wt + (size_t)(n0 + lrow) * KTOT + tap * CIN + ci0) + loff;
        cp16(stB + lrow * 80 + loff, srcB, 16);
        cp16(stB + lrow * 80 + loff + 16, srcB + 16, 16);
    };

    loadChunk(0); CP_COMMIT();
    loadChunk(1); CP_COMMIT();

    for (int c = 0; c < NC; ++c) {
        if (c + 1 < NC) { CP_WAIT1(); } else { CP_WAIT0(); }
        __syncthreads();
        if (c + 2 < NC) { loadChunk(c + 2); CP_COMMIT(); }

        const uint32_t stA = sb + (c % 3) * STG;
        const uint32_t stB = stA + 10240;
#pragma unroll
        for (int ks = 0; ks < 2; ++ks) {
            uint32_t afr[2][4];
#pragma unroll
            for (int i = 0; i < 2; ++i) {
                const int r = warp_m * 32 + i * 16 + (lane & 15);
                ldsm4(afr[i], stA + r * 80 + ks * 32 + (lane >> 4) * 16);
            }
            uint32_t bfr[8][2];
#pragma unroll
            for (int j2 = 0; j2 < 4; ++j2) {
                const int nb = warp_n * 64 + j2 * 16;
                const int g = lane >> 3;
                const int row = nb + (g >> 1) * 8 + (lane & 7);
                uint32_t r4[4];
                ldsm4(r4, stB + row * 80 + ks * 32 + (g & 1) * 16);
                bfr[j2 * 2 + 0][0] = r4[0]; bfr[j2 * 2 + 0][1] = r4[1];
                bfr[j2 * 2 + 1][0] = r4[2]; bfr[j2 * 2 + 1][1] = r4[3];
            }
#pragma unroll
            for (int i = 0; i < 2; ++i)
#pragma unroll
                for (int j = 0; j < 8; ++j) mma16816(acc[i][j], afr[i], bfr[j]);
        }
        __syncthreads();
    }

    // epilogue: bias + relu -> bf16
#pragma unroll
    for (int i = 0; i < 2; ++i) {
        const int row0 = m0 + warp_m * 32 + i * 16 + (lane >> 2);
#pragma unroll
        for (int j = 0; j < 8; ++j) {
            const int col0 = n0 + warp_n * 64 + j * 8 + 2 * (lane & 3);
            const float2 bv = *(const float2*)&bias[col0];
            float v0 = fmaxf(acc[i][j][0] + bv.x, 0.f);
            float v1 = fmaxf(acc[i][j][1] + bv.y, 0.f);
            float v2 = fmaxf(acc[i][j][2] + bv.x, 0.f);
            float v3 = fmaxf(acc[i][j][3] + bv.y, 0.f);
            __nv_bfloat162 p0 = __floats2bfloat162_rn(v0, v1);
            __nv_bfloat162 p1 = __floats2bfloat162_rn(v2, v3);
            *(uint32_t*)(outp + (size_t)row0 * HID + col0) = *(uint32_t*)&p0;
            *(uint32_t*)(outp + (size_t)(row0 + 8) * HID + col0) = *(uint32_t*)&p1;
        }
    }
}

// ---------------- offset head: 1x1 conv (512 -> 2) + vertex add ----------------
__global__ void head_kernel(const unsigned short* __restrict__ h,
                            const float* __restrict__ w_off,
                            const float* __restrict__ vtx,
                            float* __restrict__ out) {
    __shared__ float wsh[HID * 2];
    const int tid = threadIdx.x;
    for (int i = tid; i < HID * 2; i += 256) wsh[i] = w_off[i];
    __syncthreads();

    const int warp = tid >> 5, lane = tid & 31;
    const int p = blockIdx.x * 8 + warp;
    const __nv_bfloat16* hp = (const __nv_bfloat16*)(h + (size_t)p * HID);

    float s0 = 0.f, s1 = 0.f;
#pragma unroll
    for (int i = lane; i < HID; i += 32) {
        const float v = __bfloat162float(hp[i]);
        s0 += v * wsh[2 * i + 0];
        s1 += v * wsh[2 * i + 1];
    }
#pragma unroll
    for (int o = 16; o > 0; o >>= 1) {
        s0 += __shfl_down_sync(0xFFFFFFFFu, s0, o);
        s1 += __shfl_down_sync(0xFFFFFFFFu, s1, o);
    }
    if (lane == 0) {
        out[2 * p + 0] = vtx[2 * p + 0] + s0;
        out[2 * p + 1] = vtx[2 * p + 1] + s1;
    }
}

// ---------------- launch ----------------
extern "C" void kernel_launch(void* const* d_in, const int* in_sizes, int n_in,
                              void* d_out, int out_size) {
    (void)in_sizes; (void)n_in; (void)out_size;
    const float* vertices = (const float*)d_in[0];
    const float* features = (const float*)d_in[1];
    const float* w[6];
    const float* bb[6];
    for (int i = 0; i < 6; ++i) {
        w[i]  = (const float*)d_in[2 + 2 * i];
        bb[i] = (const float*)d_in[3 + 2 * i];
    }
    const float* w_off = (const float*)d_in[14];

    unsigned short *act0 = nullptr, *act1 = nullptr, *wtbase = nullptr;
    cudaGetSymbolAddress((void**)&act0, g_act0);
    cudaGetSymbolAddress((void**)&act1, g_act1);
    cudaGetSymbolAddress((void**)&wtbase, g_wt);

    const int SMEM_BYTES = 3 * 20480;   // 60 KB
    cudaFuncSetAttribute(conv_mma<CDIM>,
                         cudaFuncAttributeMaxDynamicSharedMemorySize, SMEM_BYTES);
    cudaFuncSetAttribute(conv_mma<HID>,
                         cudaFuncAttributeMaxDynamicSharedMemorySize, SMEM_BYTES);

    // 1) weight transpose+convert (6 layers)
    unsigned short* wts[6];
    for (int i = 0; i < 6; ++i) wts[i] = wtbase + (size_t)i * (HID * 3 * HID);
    {
        dim3 blk(32, 8);
        wconv_kernel<<<dim3(3 * CDIM / 32, HID / 32), blk>>>(w[0], wts[0], 3 * CDIM);
        for (int i = 1; i < 6; ++i)
            wconv_kernel<<<dim3(3 * HID / 32, HID / 32), blk>>>(w[i], wts[i], 3 * HID);
    }

    // 2) sampling -> act0 [8192, 256] bf16
    sample_kernel<<<MTOT / 4, 256>>>(vertices, features, act0);

    // 3) conv stack (rates 1,3,9,9,3,1)
    dim3 grid(MTOT / 128, HID / 128);
    conv_mma<CDIM><<<grid, 256, SMEM_BYTES>>>(act0, wts[0], bb[0], act1, 1);
    conv_mma<HID ><<<grid, 256, SMEM_BYTES>>>(act1, wts[1], bb[1], act0, 3);
    conv_mma<HID ><<<grid, 256, SMEM_BYTES>>>(act0, wts[2], bb[2], act1, 9);
    conv_mma<HID ><<<grid, 256, SMEM_BYTES>>>(act1, wts[3], bb[3], act0, 9);
    conv_mma<HID ><<<grid, 256, SMEM_BYTES>>>(act0, wts[4], bb[4], act1, 3);
    conv_mma<HID ><<<grid, 256, SMEM_BYTES>>>(act1, wts[5], bb[5], act0, 1);

    // 4) head + vertex add
    head_kernel<<<MTOT / 8, 256>>>(act0, w_off, vertices, (float*)d_out);
}